// round 2
// baseline (speedup 1.0000x reference)
#include <cuda_runtime.h>
#include <stdint.h>

#define NUM_FIELDS 10
#define VOCAB      100000
#define EMBED      16            // floats per embedding row (64 bytes)
#define BATCH      16384
#define NPAIRS     45            // C(10,2)

// triu_indices(10, k=1): pair p -> (ii[p], jj[p]) with ii < jj
__constant__ unsigned char c_ii[NPAIRS] = {
    0,0,0,0,0,0,0,0,0,
    1,1,1,1,1,1,1,1,
    2,2,2,2,2,2,2,
    3,3,3,3,3,3,
    4,4,4,4,4,
    5,5,5,5,
    6,6,6,
    7,7,
    8
};
__constant__ unsigned char c_jj[NPAIRS] = {
    1,2,3,4,5,6,7,8,9,
    2,3,4,5,6,7,8,9,
    3,4,5,6,7,8,9,
    4,5,6,7,8,9,
    5,6,7,8,9,
    6,7,8,9,
    7,8,9,
    8,9,
    9
};

// One thread per (batch, pair). Each thread:
//   - 2 cached int32 index loads (L1/L2 hot: 45 threads per b share them)
//   - 8 independent float4 gathers (two 64-byte embedding rows) -> MLP = 8
//   - 4 coalesced float4 stores (adjacent threads write adjacent 64B chunks)
__global__ __launch_bounds__(256)
void ffm_kernel(const int*    __restrict__ x,      // int32 (16384, 10)
                const float4* __restrict__ emb,    // (10, 1e6, 16) as float4[40M]
                float4*       __restrict__ out)    // (B, 45, 16) as float4
{
    int gid = blockIdx.x * blockDim.x + threadIdx.x;
    if (gid >= BATCH * NPAIRS) return;

    int b = gid / NPAIRS;
    int p = gid - b * NPAIRS;
    int i = c_ii[p];
    int j = c_jj[p];

    int xi = x[b * NUM_FIELDS + i];
    int xj = x[b * NUM_FIELDS + j];
    // Safety clamp: a dtype mismatch becomes a rel_err signal, not a crash.
    xi = min(max(xi, 0), VOCAB - 1);
    xj = min(max(xj, 0), VOCAB - 1);

    // out[b,p] = emb[j, x[b,i]+i*V] * emb[i, x[b,j]+j*V]
    size_t rowA = (size_t)j * (NUM_FIELDS * (size_t)VOCAB) + (size_t)xi + (size_t)i * VOCAB;
    size_t rowB = (size_t)i * (NUM_FIELDS * (size_t)VOCAB) + (size_t)xj + (size_t)j * VOCAB;

    const float4* A  = emb + rowA * (EMBED / 4);
    const float4* Bp = emb + rowB * (EMBED / 4);

    // Issue all 8 loads before consuming -> max memory-level parallelism
    float4 a0 = A[0], a1 = A[1], a2 = A[2], a3 = A[3];
    float4 b0 = Bp[0], b1 = Bp[1], b2 = Bp[2], b3 = Bp[3];

    float4 o0, o1, o2, o3;
    o0.x = a0.x * b0.x; o0.y = a0.y * b0.y; o0.z = a0.z * b0.z; o0.w = a0.w * b0.w;
    o1.x = a1.x * b1.x; o1.y = a1.y * b1.y; o1.z = a1.z * b1.z; o1.w = a1.w * b1.w;
    o2.x = a2.x * b2.x; o2.y = a2.y * b2.y; o2.z = a2.z * b2.z; o2.w = a2.w * b2.w;
    o3.x = a3.x * b3.x; o3.y = a3.y * b3.y; o3.z = a3.z * b3.z; o3.w = a3.w * b3.w;

    float4* dst = out + (size_t)gid * (EMBED / 4);
    dst[0] = o0; dst[1] = o1; dst[2] = o2; dst[3] = o3;
}

extern "C" void kernel_launch(void* const* d_in, const int* in_sizes, int n_in,
                              void* d_out, int out_size)
{
    const int*    x   = (const int*)d_in[0];      // indices (int32 on device)
    const float4* emb = (const float4*)d_in[1];   // float32 (10, 1e6, 16)
    float4*       out = (float4*)d_out;           // float32 (16384, 45, 16)

    const int total = BATCH * NPAIRS;             // 737280 threads
    const int block = 256;
    const int grid  = (total + block - 1) / block;
    ffm_kernel<<<grid, block>>>(x, emb, out);
}

// round 3
// speedup vs baseline: 1.6567x; 1.6567x over previous
#include <cuda_runtime.h>
#include <stdint.h>

#define NUM_FIELDS 10
#define VOCAB      100000
#define EMBED      16            // floats per embedding row (64 bytes)
#define BATCH      16384
#define NPAIRS     45            // C(10,2)

// triu_indices(10, k=1): pair p -> (ii[p], jj[p]) with ii < jj
__constant__ unsigned char c_ii[NPAIRS] = {
    0,0,0,0,0,0,0,0,0,
    1,1,1,1,1,1,1,1,
    2,2,2,2,2,2,2,
    3,3,3,3,3,3,
    4,4,4,4,4,
    5,5,5,5,
    6,6,6,
    7,7,
    8
};
__constant__ unsigned char c_jj[NPAIRS] = {
    1,2,3,4,5,6,7,8,9,
    2,3,4,5,6,7,8,9,
    3,4,5,6,7,8,9,
    4,5,6,7,8,9,
    5,6,7,8,9,
    6,7,8,9,
    7,8,9,
    8,9,
    9
};

// 4 lanes per (batch, pair): lane q loads float4 q of rowA and rowB.
// -> each 64B embedding row is fetched by 4 CONTIGUOUS lanes in ONE LDG
//    instruction (1 L1tex wavefront per row instead of 4), stores coalesced.
__global__ __launch_bounds__(256)
void ffm_kernel(const int*    __restrict__ x,      // int32 (16384, 10)
                const float4* __restrict__ emb,    // (10, 1e6, 16) as float4[40M]
                float4*       __restrict__ out)    // (16384, 45, 16) as float4
{
    int gid = blockIdx.x * blockDim.x + threadIdx.x;
    if (gid >= BATCH * NPAIRS * 4) return;

    int q = gid & 3;          // which float4 of the row
    int e = gid >> 2;         // linear (b, pair)
    int b = e / NPAIRS;
    int p = e - b * NPAIRS;
    int i = c_ii[p];
    int j = c_jj[p];

    // 4 lanes of a quad read the same address -> broadcast, L1-hot
    int xi = x[b * NUM_FIELDS + i];
    int xj = x[b * NUM_FIELDS + j];
    xi = min(max(xi, 0), VOCAB - 1);
    xj = min(max(xj, 0), VOCAB - 1);

    // out[b,p] = emb[j, x[b,i]+i*V] * emb[i, x[b,j]+j*V]
    size_t rowA = (size_t)j * (NUM_FIELDS * (size_t)VOCAB) + (size_t)xi + (size_t)i * VOCAB;
    size_t rowB = (size_t)i * (NUM_FIELDS * (size_t)VOCAB) + (size_t)xj + (size_t)j * VOCAB;

    // No reuse of embedding rows (each used exactly once) -> streaming hints
    float4 a = __ldcs(emb + rowA * (EMBED / 4) + q);
    float4 v = __ldcs(emb + rowB * (EMBED / 4) + q);

    float4 o;
    o.x = a.x * v.x;
    o.y = a.y * v.y;
    o.z = a.z * v.z;
    o.w = a.w * v.w;

    __stcs(out + (size_t)e * (EMBED / 4) + q, o);
}

extern "C" void kernel_launch(void* const* d_in, const int* in_sizes, int n_in,
                              void* d_out, int out_size)
{
    const int*    x   = (const int*)d_in[0];      // indices (int32 on device)
    const float4* emb = (const float4*)d_in[1];   // float32 (10, 1e6, 16)
    float4*       out = (float4*)d_out;           // float32 (16384, 45, 16)

    const int total = BATCH * NPAIRS * 4;         // 2,949,120 threads
    const int block = 256;
    const int grid  = (total + block - 1) / block;
    ffm_kernel<<<grid, block>>>(x, emb, out);
}